// round 10
// baseline (speedup 1.0000x reference)
#include <cuda_runtime.h>
#include <cuda_bf16.h>
#include <cstdint>

// Problem constants
#define BATCH    16384
#define IN_SIZE  448
#define OUT_SIZE 448
#define W_TOT    14336
#define NE       64
#define NB       128
#define NTHREADS 512
#define PTHREADS 128
#define NHB      (BATCH / PTHREADS)   // 128
#define MAX_TILES 192
#define GRID_COMPUTE 148

// B (W^T) image layout per element, padded row strides (odd*16 -> conflict-free)
#define B0_STR 208
#define B1_STR 144
#define B2_STR 80
#define OFF_B0H 0
#define OFF_B0L 19968
#define OFF_B1H 39936
#define OFF_B1L 49152
#define OFF_B2H 58368
#define OFF_B2L 60928
#define IMG_BYTES 63488

// Per-node repacked x blob (hi/lo bf16, padded per-slice)
#define XN_BYTES 2080
#define XOFF_S0H 0
#define XOFF_S0L 208
#define XOFF_S1(m) (416 + 288 * (m))   // hi; lo at +144
#define XOFF_S2(m) (1280 + 160 * (m))  // hi; lo at +80

__device__ unsigned char g_Wimg[(size_t)NE * IMG_BYTES];
__device__ unsigned char g_xre[(size_t)BATCH * XN_BYTES];
__device__ int g_hist[NHB][NE];
__device__ int g_perm[BATCH];
__device__ int g_ntiles;
__device__ int g_tile_ctr;
__device__ int g_tile_e[MAX_TILES];
__device__ int g_tile_r0[MAX_TILES];
__device__ int g_tile_R[MAX_TILES];

__device__ __forceinline__ int get_idx(const void* p, int b, int is64) {
    if (is64) return (int)((const long long*)p)[b];
    return ((const int*)p)[b];
}
__device__ __forceinline__ int detect_is64(const void* idxp, int tid, int* s_flag) {
    if (tid < 32) {
        long long v = ((const long long*)idxp)[tid];
        unsigned ok = __ballot_sync(0xFFFFFFFFu, v >= 0 && v < 64);
        if (tid == 0) *s_flag = (ok == 0xFFFFFFFFu) ? 1 : 0;
    }
    __syncthreads();
    return *s_flag;
}
__device__ __forceinline__ uint32_t pk2(float a, float b,
                                        float* la, float* lb) {
    __nv_bfloat16 ha = __float2bfloat16_rn(a);
    __nv_bfloat16 hb = __float2bfloat16_rn(b);
    *la = a - __bfloat162float(ha);
    *lb = b - __bfloat162float(hb);
    uint16_t ua, ub;
    memcpy(&ua, &ha, 2); memcpy(&ub, &hb, 2);
    return (uint32_t)ua | ((uint32_t)ub << 16);
}
__device__ __forceinline__ uint32_t pk2lo(float la, float lb) {
    __nv_bfloat16 a = __float2bfloat16_rn(la);
    __nv_bfloat16 b = __float2bfloat16_rn(lb);
    uint16_t ua, ub;
    memcpy(&ua, &a, 2); memcpy(&ub, &b, 2);
    return (uint32_t)ua | ((uint32_t)ub << 16);
}

// ---------------------------------------------------------------------------
// K0a: W -> transposed + padded hi/lo bf16 images
// ---------------------------------------------------------------------------
__global__ void wconv_kernel(const float* __restrict__ W) {
    int e = blockIdx.x, tid = threadIdx.x;
    const float* We = W + (size_t)e * W_TOT;
    unsigned char* img = g_Wimg + (size_t)e * IMG_BYTES;
    // seg0: B[o][k] = W[k*96+o], o<96, k<96 (pack pairs of k)
    for (int i = tid; i < 96 * 48; i += 256) {
        int o = i / 48, k2 = i - 48 * (i / 48);
        int k = 2 * k2;
        float la, lb;
        uint32_t h = pk2(We[k * 96 + o], We[(k + 1) * 96 + o], &la, &lb);
        *(uint32_t*)(img + OFF_B0H + o * B0_STR + 2 * k) = h;
        *(uint32_t*)(img + OFF_B0L + o * B0_STR + 2 * k) = pk2lo(la, lb);
    }
    // seg1: B[o][k] = W[9216 + k*64 + o], o<64, k<64
    for (int i = tid; i < 64 * 32; i += 256) {
        int o = i >> 5, k = (i & 31) * 2;
        float la, lb;
        uint32_t h = pk2(We[9216 + k * 64 + o], We[9216 + (k + 1) * 64 + o], &la, &lb);
        *(uint32_t*)(img + OFF_B1H + o * B1_STR + 2 * k) = h;
        *(uint32_t*)(img + OFF_B1L + o * B1_STR + 2 * k) = pk2lo(la, lb);
    }
    // seg2: B[o][k] = W[13312 + k*32 + o], o<32, k<32
    for (int i = tid; i < 32 * 16; i += 256) {
        int o = i >> 4, k = (i & 15) * 2;
        float la, lb;
        uint32_t h = pk2(We[13312 + k * 32 + o], We[13312 + (k + 1) * 32 + o], &la, &lb);
        *(uint32_t*)(img + OFF_B2H + o * B2_STR + 2 * k) = h;
        *(uint32_t*)(img + OFF_B2L + o * B2_STR + 2 * k) = pk2lo(la, lb);
    }
}

// ---------------------------------------------------------------------------
// K0b: x -> per-node repacked hi/lo bf16 blobs (16 nodes/block, 128 thr)
// ---------------------------------------------------------------------------
__global__ void xconv_kernel(const float* __restrict__ x) {
    __shared__ float sx[16][IN_SIZE];
    int tid = threadIdx.x, blk = blockIdx.x;
    for (int i = tid; i < 16 * 112; i += 128) {
        int n = i / 112, q = i - 112 * n;
        *(float4*)&sx[n][4 * q] =
            *(const float4*)(x + (size_t)(blk * 16 + n) * IN_SIZE + 4 * q);
    }
    __syncthreads();
    int n = tid >> 3, s = tid & 7;
    const float* row = sx[n];
    unsigned char* out = g_xre + (size_t)(blk * 16 + n) * XN_BYTES;
    // seg0: k in [12s, 12s+12)
    #pragma unroll
    for (int j = 0; j < 6; j++) {
        int k = 12 * s + 2 * j;
        float la, lb;
        uint32_t h = pk2(row[k], row[k + 1], &la, &lb);
        *(uint32_t*)(out + XOFF_S0H + 2 * k) = h;
        *(uint32_t*)(out + XOFF_S0L + 2 * k) = pk2lo(la, lb);
    }
    // seg1: m 0..2, k in [8s, 8s+8)
    #pragma unroll
    for (int m = 0; m < 3; m++)
        #pragma unroll
        for (int j = 0; j < 4; j++) {
            int k = 8 * s + 2 * j;
            float la, lb;
            uint32_t h = pk2(row[96 + 3 * k + m], row[96 + 3 * (k + 1) + m], &la, &lb);
            *(uint32_t*)(out + XOFF_S1(m) + 2 * k) = h;
            *(uint32_t*)(out + XOFF_S1(m) + 144 + 2 * k) = pk2lo(la, lb);
        }
    // seg2: m 0..4, k in [4s, 4s+4)
    #pragma unroll
    for (int m = 0; m < 5; m++)
        #pragma unroll
        for (int j = 0; j < 2; j++) {
            int k = 4 * s + 2 * j;
            float la, lb;
            uint32_t h = pk2(row[288 + 5 * k + m], row[288 + 5 * (k + 1) + m], &la, &lb);
            *(uint32_t*)(out + XOFF_S2(m) + 2 * k) = h;
            *(uint32_t*)(out + XOFF_S2(m) + 80 + 2 * k) = pk2lo(la, lb);
        }
}

// ---------------------------------------------------------------------------
// K1/K2: histogram + fused scan/scatter/tile-build (NB=128 tiles)
// ---------------------------------------------------------------------------
__global__ void hist_kernel(const void* idxp) {
    __shared__ int h[NE];
    __shared__ int sflag;
    int tid = threadIdx.x;
    if (tid < NE) h[tid] = 0;
    int is64 = detect_is64(idxp, tid, &sflag);
    int b = blockIdx.x * PTHREADS + tid;
    int e = get_idx(idxp, b, is64);
    atomicAdd(&h[e], 1);
    __syncthreads();
    if (tid < NE) g_hist[blockIdx.x][tid] = h[tid];
}

__global__ void finish_kernel(const void* idxp) {
    __shared__ int preS[NE], totS[NE], offS[NE];
    __shared__ int sflag;
    int t = threadIdx.x, b = blockIdx.x;
    int is64 = detect_is64(idxp, t, &sflag);
    if (t < NE) {
        int pre = 0, tot = 0;
        #pragma unroll 8
        for (int bb = 0; bb < NHB; bb++) {
            int v = g_hist[bb][t];
            tot += v;
            if (bb < b) pre += v;
        }
        preS[t] = pre; totS[t] = tot;
    }
    __syncthreads();
    if (t == 0) {
        int s = 0;
        for (int e2 = 0; e2 < NE; e2++) { offS[e2] = s; s += totS[e2]; }
    }
    __syncthreads();
    int my = b * PTHREADS + t;
    int e = get_idx(idxp, my, is64);
    int rank = atomicAdd(&preS[e], 1);
    g_perm[offS[e] + rank] = my;

    if (b == 0 && t == 0) {
        int ts = 0;
        for (int e2 = 0; e2 < NE; e2++) {
            int c = totS[e2], o = offS[e2], nf = c >> 7;
            for (int i = 0; i < nf; i++) {
                g_tile_e[ts] = e2; g_tile_r0[ts] = o + (i << 7); g_tile_R[ts] = NB; ts++;
            }
        }
        for (int e2 = 0; e2 < NE; e2++) {
            int c = totS[e2], o = offS[e2], nf = c >> 7, rem = c & 127;
            if (rem) {
                g_tile_e[ts] = e2; g_tile_r0[ts] = o + (nf << 7); g_tile_R[ts] = rem; ts++;
            }
        }
        g_ntiles = ts;
        g_tile_ctr = 0;
    }
}

// ---------------------------------------------------------------------------
// Compute: classic HMMA (mma.sync bf16) with 3-term split
// SMEM: [0,16) tile | [16,528) nodes | A at 1024 (53248) | B at 54272 (63488)
// ---------------------------------------------------------------------------
#define A_OFF 1024
#define BB_OFF (1024 + 53248)
#define SMEM_BYTES (1024 + 53248 + 63488)

__device__ __forceinline__ uint32_t smem_u32(const void* p) {
    uint32_t a;
    asm("{ .reg .u64 t; cvta.to.shared.u64 t, %1; cvt.u32.u64 %0, t; }"
        : "=r"(a) : "l"(p));
    return a;
}
__device__ __forceinline__ void cpa16(uint32_t dst, const void* src) {
    asm volatile("cp.async.cg.shared.global [%0], [%1], 16;\n" :: "r"(dst), "l"(src));
}
__device__ __forceinline__ void cpa_wait() {
    asm volatile("cp.async.commit_group;\ncp.async.wait_group 0;\n" ::: "memory");
}
__device__ __forceinline__ void ldm4(uint32_t* r, uint32_t a) {
    asm volatile("ldmatrix.sync.aligned.m8n8.x4.shared.b16 {%0,%1,%2,%3}, [%4];"
                 : "=r"(r[0]), "=r"(r[1]), "=r"(r[2]), "=r"(r[3]) : "r"(a));
}
__device__ __forceinline__ void mma16816(float* d, const uint32_t* a, const uint32_t* b) {
    asm volatile(
        "mma.sync.aligned.m16n8k16.row.col.f32.bf16.bf16.f32 "
        "{%0,%1,%2,%3}, {%4,%5,%6,%7}, {%8,%9}, {%0,%1,%2,%3};"
        : "+f"(d[0]), "+f"(d[1]), "+f"(d[2]), "+f"(d[3])
        : "r"(a[0]), "r"(a[1]), "r"(a[2]), "r"(a[3]), "r"(b[0]), "r"(b[1]));
}

__global__ void __launch_bounds__(NTHREADS)
compute_kernel(float* __restrict__ y)
{
    extern __shared__ unsigned char sm[];
    int* s_tile = (int*)(sm);
    int* s_node = (int*)(sm + 16);

    const int tid = threadIdx.x, lane = tid & 31, wid = tid >> 5;
    const int wr = wid & 7, wc = wid >> 3;        // row stripe / col half
    const uint32_t base_u = smem_u32(sm);
    const uint32_t sA = base_u + A_OFF;
    const uint32_t sB = base_u + BB_OFF;
    const int nt = g_ntiles;

    // ldmatrix lane-address components
    const int a_row = lane & 15;                  // A: rows, +16B for k+8
    const int a_k16 = (lane >> 4) << 4;
    const int b_row = (lane & 7) + ((lane >> 4) << 3);   // B: n rows of pair
    const int b_k16 = ((lane >> 3) & 1) << 4;

    for (int iter = 0; iter < MAX_TILES + 4; iter++) {
        if (tid == 0) *s_tile = atomicAdd(&g_tile_ctr, 1);
        __syncthreads();
        const int t = *s_tile;
        if (t >= nt) break;
        const int e  = g_tile_e[t];
        const int r0 = g_tile_r0[t];
        const int R  = g_tile_R[t];
        if (tid < NB) s_node[tid] = g_perm[r0 + min(tid, R - 1)];
        __syncthreads();

        // Stage B images (63488B linear) + A seg0 (hi/lo, stride 208)
        {
            const unsigned char* bs = g_Wimg + (size_t)e * IMG_BYTES;
            for (int i = tid; i < IMG_BYTES / 16; i += NTHREADS)
                cpa16(sB + 16u * i, bs + 16 * i);
            for (int i = tid; i < R * 26; i += NTHREADS) {
                int nb = i / 26, j = i - 26 * nb;
                const unsigned char* src = g_xre + (size_t)s_node[nb] * XN_BYTES;
                if (j < 13) cpa16(sA + nb * 208 + 16 * j, src + 16 * j);
                else cpa16(sA + 26624 + nb * 208 + 16 * (j - 13), src + 208 + 16 * (j - 13));
            }
            cpa_wait();
        }
        __syncthreads();

        // ===== seg0: M=128 N=96 K=96 =====
        if (16 * wr < R) {
            float c[6][4];
            #pragma unroll
            for (int j = 0; j < 6; j++)
                #pragma unroll
                for (int q = 0; q < 4; q++) c[j][q] = 0.f;
            const uint32_t ah = sA + (16 * wr + a_row) * 208 + a_k16;
            const uint32_t al = ah + 26624;
            const uint32_t bh = sB + OFF_B0H + (48 * wc + b_row) * 208 + b_k16;
            const uint32_t bl = sB + OFF_B0L + (48 * wc + b_row) * 208 + b_k16;
            #pragma unroll
            for (int kk = 0; kk < 6; kk++) {
                uint32_t A[4], Al[4];
                ldm4(A, ah + 32 * kk);
                ldm4(Al, al + 32 * kk);
                #pragma unroll
                for (int p = 0; p < 3; p++) {
                    uint32_t Bh[4], Bl[4];
                    ldm4(Bh, bh + p * (16 * 208) + 32 * kk);
                    ldm4(Bl, bl + p * (16 * 208) + 32 * kk);
                    mma16816(c[2 * p], A, Bh);
                    mma16816(c[2 * p], Al, Bh);
                    mma16816(c[2 * p], A, Bl);
                    mma16816(c[2 * p + 1], A, Bh + 2);
                    mma16816(c[2 * p + 1], Al, Bh + 2);
                    mma16816(c[2 * p + 1], A, Bl + 2);
                }
            }
            int rA = 16 * wr + (lane >> 2), rB = rA + 8;
            int cb = 48 * wc + 2 * (lane & 3);
            if (rA < R) {
                float* yp = y + (size_t)s_node[rA] * OUT_SIZE;
                #pragma unroll
                for (int j = 0; j < 6; j++)
                    *(float2*)(yp + cb + 8 * j) = make_float2(c[j][0], c[j][1]);
            }
            if (rB < R) {
                float* yp = y + (size_t)s_node[rB] * OUT_SIZE;
                #pragma unroll
                for (int j = 0; j < 6; j++)
                    *(float2*)(yp + cb + 8 * j) = make_float2(c[j][2], c[j][3]);
            }
        }
        __syncthreads();

        // ===== seg1: 3x (M=128 N=64 K=64), stride 144 =====
        for (int m = 0; m < 3; m++) {
            for (int i = tid; i < R * 18; i += NTHREADS) {
                int nb = i / 18, j = i - 18 * nb;
                const unsigned char* src =
                    g_xre + (size_t)s_node[nb] * XN_BYTES + XOFF_S1(m);
                if (j < 9) cpa16(sA + nb * 144 + 16 * j, src + 16 * j);
                else cpa16(sA + 18432 + nb * 144 + 16 * (j - 9), src + 144 + 16 * (j - 9));
            }
            cpa_wait();
            __syncthreads();
            if (16 * wr < R) {
                float c[4][4];
                #pragma unroll
                for (int j = 0; j < 4; j++)
                    #pragma unroll
                    for (int q = 0; q < 4; q++) c[j][q] = 0.f;
                const uint32_t ah = sA + (16 * wr + a_row) * 144 + a_k16;
                const uint32_t al = ah + 18432;
                const uint32_t bh = sB + OFF_B1H + (32 * wc + b_row) * 144 + b_k16;
                const uint32_t bl = sB + OFF_B1L + (32 * wc + b_row) * 144 + b_k16;
                #pragma unroll
                for (int kk = 0; kk < 4; kk++) {
                    uint32_t A[4], Al[4];
                    ldm4(A, ah + 32 * kk);
                    ldm4(Al, al + 32 * kk);
                    #pragma unroll
                    for (int p = 0; p < 2; p++) {
                        uint32_t Bh[4], Bl[4];
                        ldm4(Bh, bh + p * (16 * 144) + 32 * kk);
                        ldm4(Bl, bl + p * (16 * 144) + 32 * kk);
                        mma16816(c[2 * p], A, Bh);
                        mma16816(c[2 * p], Al, Bh);
                        mma16816(c[2 * p], A, Bl);
                        mma16816(c[2 * p + 1], A, Bh + 2);
                        mma16816(c[2 * p + 1], Al, Bh + 2);
                        mma16816(c[2 * p + 1], A, Bl + 2);
                    }
                }
                int rA = 16 * wr + (lane >> 2), rB = rA + 8;
                int cb = 32 * wc + 2 * (lane & 3);
                if (rA < R) {
                    float* yp = y + (size_t)s_node[rA] * OUT_SIZE + 96 + m;
                    #pragma unroll
                    for (int j = 0; j < 4; j++) {
                        yp[3 * (cb + 8 * j)] = c[j][0];
                        yp[3 * (cb + 8 * j + 1)] = c[j][1];
                    }
                }
                if (rB < R) {
                    float* yp = y + (size_t)s_node[rB] * OUT_SIZE + 96 + m;
                    #pragma unroll
                    for (int j = 0; j < 4; j++) {
                        yp[3 * (cb + 8 * j)] = c[j][2];
                        yp[3 * (cb + 8 * j + 1)] = c[j][3];
                    }
                }
            }
            __syncthreads();
        }

        // ===== seg2: 5x (M=128 N=32 K=32), stride 80 =====
        for (int m = 0; m < 5; m++) {
            for (int i = tid; i < R * 10; i += NTHREADS) {
                int nb = i / 10, j = i - 10 * nb;
                const unsigned char* src =
                    g_xre + (size_t)s_node[nb] * XN_BYTES + XOFF_S2(m);
                if (j < 5) cpa16(sA + nb * 80 + 16 * j, src + 16 * j);
                else cpa16(sA + 10240 + nb * 80 + 16 * (j - 5), src + 80 + 16 * (j - 5));
            }
            cpa_wait();
            __syncthreads();
            if (16 * wr < R) {
                float c[2][4];
                #pragma unroll
                for (int j = 0; j < 2; j++)
                    #pragma unroll
                    for (int q = 0; q < 4; q++) c[j][q] = 0.f;
                const uint32_t ah = sA + (16 * wr + a_row) * 80 + a_k16;
                const uint32_t al = ah + 10240;
                const uint32_t bh = sB + OFF_B2H + (16 * wc + b_row) * 80 + b_k16;
                const uint32_t bl = sB + OFF_B2L + (16 * wc + b_row) * 80 + b_k16;
                #pragma unroll
                for (int kk = 0; kk < 2; kk++) {
                    uint32_t A[4], Al[4];
                    ldm4(A, ah + 32 * kk);
                    ldm4(Al, al + 32 * kk);
                    uint32_t Bh[4], Bl[4];
                    ldm4(Bh, bh + 32 * kk);
                    ldm4(Bl, bl + 32 * kk);
                    mma16816(c[0], A, Bh);
                    mma16816(c[0], Al, Bh);
                    mma16816(c[0], A, Bl);
                    mma16816(c[1], A, Bh + 2);
                    mma16816(c[1], Al, Bh + 2);
                    mma16816(c[1], A, Bl + 2);
                }
                int rA = 16 * wr + (lane >> 2), rB = rA + 8;
                int cb = 16 * wc + 2 * (lane & 3);
                if (rA < R) {
                    float* yp = y + (size_t)s_node[rA] * OUT_SIZE + 288 + m;
                    #pragma unroll
                    for (int j = 0; j < 2; j++) {
                        yp[5 * (cb + 8 * j)] = c[j][0];
                        yp[5 * (cb + 8 * j + 1)] = c[j][1];
                    }
                }
                if (rB < R) {
                    float* yp = y + (size_t)s_node[rB] * OUT_SIZE + 288 + m;
                    #pragma unroll
                    for (int j = 0; j < 2; j++) {
                        yp[5 * (cb + 8 * j)] = c[j][2];
                        yp[5 * (cb + 8 * j + 1)] = c[j][3];
                    }
                }
            }
            __syncthreads();
        }
    }
}

// ---------------------------------------------------------------------------
// Launch
// ---------------------------------------------------------------------------
extern "C" void kernel_launch(void* const* d_in, const int* in_sizes, int n_in,
                              void* d_out, int out_size)
{
    const float* W  = (const float*)d_in[0];   // [64, 14336]
    const float* x  = (const float*)d_in[1];   // [16384, 448]
    const void*  ix = d_in[2];                 // [16384] int32 or int64
    float* y = (float*)d_out;                  // [16384, 448]

    cudaFuncSetAttribute(compute_kernel,
                         cudaFuncAttributeMaxDynamicSharedMemorySize, SMEM_BYTES);

    wconv_kernel<<<NE, 256>>>(W);
    xconv_kernel<<<BATCH / 16, 128>>>(x);
    hist_kernel<<<NHB, PTHREADS>>>(ix);
    finish_kernel<<<NHB, PTHREADS>>>(ix);
    compute_kernel<<<GRID_COMPUTE, NTHREADS, SMEM_BYTES>>>(y);
}

// round 11
// speedup vs baseline: 1.4807x; 1.4807x over previous
#include <cuda_runtime.h>
#include <cuda_bf16.h>
#include <cstdint>

// Problem constants
#define BATCH    16384
#define IN_SIZE  448
#define OUT_SIZE 448
#define W_TOT    14336
#define NE       64
#define NB       128
#define NTHREADS 512
#define PTHREADS 256
#define NHB      (BATCH / PTHREADS)   // 64
#define MAX_TILES 192
#define GRID_COMPUTE 148

// B (W^T) image layout per element, padded row strides (odd*16 -> conflict-free)
#define B0_STR 208
#define B1_STR 144
#define B2_STR 80
#define OFF_B0H 0
#define OFF_B0L 19968
#define OFF_B1H 39936
#define OFF_B1L 49152
#define OFF_B2H 58368
#define OFF_B2L 60928
#define IMG_BYTES 63488

__device__ unsigned char g_Wimg[(size_t)NE * IMG_BYTES];
__device__ int g_hist[NHB][NE];
__device__ int g_perm[BATCH];
__device__ int g_ntiles;
__device__ int g_tile_ctr;
__device__ int g_tile_e[MAX_TILES];
__device__ int g_tile_r0[MAX_TILES];
__device__ int g_tile_R[MAX_TILES];

__device__ __forceinline__ int get_idx(const void* p, int b, int is64) {
    if (is64) return (int)((const long long*)p)[b];
    return ((const int*)p)[b];
}
__device__ __forceinline__ int detect_is64(const void* idxp, int tid, int* s_flag) {
    if (tid < 32) {
        long long v = ((const long long*)idxp)[tid];
        unsigned ok = __ballot_sync(0xFFFFFFFFu, v >= 0 && v < 64);
        if (tid == 0) *s_flag = (ok == 0xFFFFFFFFu) ? 1 : 0;
    }
    __syncthreads();
    return *s_flag;
}
__device__ __forceinline__ uint32_t pk2(float a, float b, float* la, float* lb) {
    __nv_bfloat16 ha = __float2bfloat16_rn(a);
    __nv_bfloat16 hb = __float2bfloat16_rn(b);
    *la = a - __bfloat162float(ha);
    *lb = b - __bfloat162float(hb);
    uint16_t ua, ub;
    memcpy(&ua, &ha, 2); memcpy(&ub, &hb, 2);
    return (uint32_t)ua | ((uint32_t)ub << 16);
}
__device__ __forceinline__ uint32_t pk2lo(float la, float lb) {
    __nv_bfloat16 a = __float2bfloat16_rn(la);
    __nv_bfloat16 b = __float2bfloat16_rn(lb);
    uint16_t ua, ub;
    memcpy(&ua, &a, 2); memcpy(&ub, &b, 2);
    return (uint32_t)ua | ((uint32_t)ub << 16);
}

// ---------------------------------------------------------------------------
// K0: W -> transposed + padded hi/lo bf16 images
// ---------------------------------------------------------------------------
__global__ void wconv_kernel(const float* __restrict__ W) {
    int e = blockIdx.x, tid = threadIdx.x;
    const float* We = W + (size_t)e * W_TOT;
    unsigned char* img = g_Wimg + (size_t)e * IMG_BYTES;
    for (int i = tid; i < 96 * 48; i += PTHREADS) {
        int o = i / 48, k = 2 * (i - 48 * (i / 48));
        float la, lb;
        uint32_t h = pk2(We[k * 96 + o], We[(k + 1) * 96 + o], &la, &lb);
        *(uint32_t*)(img + OFF_B0H + o * B0_STR + 2 * k) = h;
        *(uint32_t*)(img + OFF_B0L + o * B0_STR + 2 * k) = pk2lo(la, lb);
    }
    for (int i = tid; i < 64 * 32; i += PTHREADS) {
        int o = i >> 5, k = (i & 31) * 2;
        float la, lb;
        uint32_t h = pk2(We[9216 + k * 64 + o], We[9216 + (k + 1) * 64 + o], &la, &lb);
        *(uint32_t*)(img + OFF_B1H + o * B1_STR + 2 * k) = h;
        *(uint32_t*)(img + OFF_B1L + o * B1_STR + 2 * k) = pk2lo(la, lb);
    }
    for (int i = tid; i < 32 * 16; i += PTHREADS) {
        int o = i >> 4, k = (i & 15) * 2;
        float la, lb;
        uint32_t h = pk2(We[13312 + k * 32 + o], We[13312 + (k + 1) * 32 + o], &la, &lb);
        *(uint32_t*)(img + OFF_B2H + o * B2_STR + 2 * k) = h;
        *(uint32_t*)(img + OFF_B2L + o * B2_STR + 2 * k) = pk2lo(la, lb);
    }
}

// ---------------------------------------------------------------------------
// K1/K2: histogram + fused scan/scatter/tile-build (64 blocks x 256 threads)
// ---------------------------------------------------------------------------
__global__ void hist_kernel(const void* idxp) {
    __shared__ int h[NE];
    __shared__ int sflag;
    int tid = threadIdx.x;
    if (tid < NE) h[tid] = 0;
    int is64 = detect_is64(idxp, tid, &sflag);
    int b = blockIdx.x * PTHREADS + tid;
    int e = get_idx(idxp, b, is64);
    atomicAdd(&h[e], 1);
    __syncthreads();
    if (tid < NE) g_hist[blockIdx.x][tid] = h[tid];
}

__global__ void finish_kernel(const void* idxp) {
    __shared__ int preS[NE], totS[NE], offS[NE];
    __shared__ int sflag;
    int t = threadIdx.x, b = blockIdx.x;
    int is64 = detect_is64(idxp, t, &sflag);
    if (t < NE) {
        int pre = 0, tot = 0;
        #pragma unroll 8
        for (int bb = 0; bb < NHB; bb++) {
            int v = g_hist[bb][t];
            tot += v;
            if (bb < b) pre += v;
        }
        preS[t] = pre; totS[t] = tot;
    }
    __syncthreads();
    if (t == 0) {
        int s = 0;
        for (int e2 = 0; e2 < NE; e2++) { offS[e2] = s; s += totS[e2]; }
    }
    __syncthreads();
    int my = b * PTHREADS + t;
    int e = get_idx(idxp, my, is64);
    int rank = atomicAdd(&preS[e], 1);
    g_perm[offS[e] + rank] = my;

    if (b == 0 && t == 0) {
        int ts = 0;
        for (int e2 = 0; e2 < NE; e2++) {
            int c = totS[e2], o = offS[e2], nf = c >> 7;
            for (int i = 0; i < nf; i++) {
                g_tile_e[ts] = e2; g_tile_r0[ts] = o + (i << 7); g_tile_R[ts] = NB; ts++;
            }
        }
        for (int e2 = 0; e2 < NE; e2++) {
            int c = totS[e2], o = offS[e2], nf = c >> 7, rem = c & 127;
            if (rem) {
                g_tile_e[ts] = e2; g_tile_r0[ts] = o + (nf << 7); g_tile_R[ts] = rem; ts++;
            }
        }
        g_ntiles = ts;
        g_tile_ctr = 0;
    }
}

// ---------------------------------------------------------------------------
// Compute: HMMA (mma.sync bf16, 3-term split) with inline f32->bf16 conversion
// SMEM: ctrl 1024 | sA bf16 53248 | sB images 63488 | sF f32 98304  = 216064
// ---------------------------------------------------------------------------
#define A_OFF  1024
#define BB_OFF (1024 + 53248)
#define SF_OFF (1024 + 53248 + 63488)
#define SMEM_BYTES (1024 + 53248 + 63488 + 98304)

__device__ __forceinline__ uint32_t smem_u32(const void* p) {
    uint32_t a;
    asm("{ .reg .u64 t; cvta.to.shared.u64 t, %1; cvt.u32.u64 %0, t; }"
        : "=r"(a) : "l"(p));
    return a;
}
__device__ __forceinline__ void cpa16(uint32_t dst, const void* src) {
    asm volatile("cp.async.cg.shared.global [%0], [%1], 16;\n" :: "r"(dst), "l"(src));
}
__device__ __forceinline__ void cpa_commit() {
    asm volatile("cp.async.commit_group;\n" ::: "memory");
}
__device__ __forceinline__ void cpa_wait() {
    asm volatile("cp.async.wait_group 0;\n" ::: "memory");
}
__device__ __forceinline__ void ldm4(uint32_t* r, uint32_t a) {
    asm volatile("ldmatrix.sync.aligned.m8n8.x4.shared.b16 {%0,%1,%2,%3}, [%4];"
                 : "=r"(r[0]), "=r"(r[1]), "=r"(r[2]), "=r"(r[3]) : "r"(a));
}
__device__ __forceinline__ void mma16816(float* d, const uint32_t* a, const uint32_t* b) {
    asm volatile(
        "mma.sync.aligned.m16n8k16.row.col.f32.bf16.bf16.f32 "
        "{%0,%1,%2,%3}, {%4,%5,%6,%7}, {%8,%9}, {%0,%1,%2,%3};"
        : "+f"(d[0]), "+f"(d[1]), "+f"(d[2]), "+f"(d[3])
        : "r"(a[0]), "r"(a[1]), "r"(a[2]), "r"(a[3]), "r"(b[0]), "r"(b[1]));
}

__global__ void __launch_bounds__(NTHREADS)
compute_kernel(const float* __restrict__ x, float* __restrict__ y)
{
    extern __shared__ unsigned char sm[];
    int* s_tile = (int*)(sm);
    int* s_node = (int*)(sm + 16);
    float* sFf = (float*)(sm + SF_OFF);

    const int tid = threadIdx.x, lane = tid & 31, wid = tid >> 5;
    const int wr = wid & 7, wc = wid >> 3;        // row stripe / col half
    const uint32_t base_u = smem_u32(sm);
    const uint32_t sA = base_u + A_OFF;
    const uint32_t sB = base_u + BB_OFF;
    const uint32_t sF = base_u + SF_OFF;
    const int nt = g_ntiles;

    // ldmatrix lane-address components (verified mapping, R10 rel_err 4.5e-6)
    const int a_row = lane & 15;
    const int a_k16 = (lane >> 4) << 4;
    const int b_row = (lane & 7) + ((lane >> 4) << 3);
    const int b_k16 = ((lane >> 3) & 1) << 4;

    for (int iter = 0; iter < MAX_TILES + 4; iter++) {
        if (tid == 0) *s_tile = atomicAdd(&g_tile_ctr, 1);
        __syncthreads();
        const int t = *s_tile;
        if (t >= nt) break;
        const int e  = g_tile_e[t];
        const int r0 = g_tile_r0[t];
        const int R  = g_tile_R[t];
        if (tid < NB) s_node[tid] = g_perm[r0 + min(tid, R - 1)];
        __syncthreads();

        // Stage B images + seg0 f32 slice (96 floats/node)
        {
            const unsigned char* bs = g_Wimg + (size_t)e * IMG_BYTES;
            for (int i = tid; i < IMG_BYTES / 16; i += NTHREADS)
                cpa16(sB + 16u * i, bs + 16 * i);
            for (int i = tid; i < R * 24; i += NTHREADS) {
                int nb = i / 24, o = i - 24 * nb;
                cpa16(sF + nb * 384 + 16 * o, x + (size_t)s_node[nb] * IN_SIZE + 4 * o);
            }
            cpa_commit(); cpa_wait();
        }
        __syncthreads();

        // Convert seg0: f32 -> hi/lo bf16, A stride 208
        for (int i = tid; i < R * 48; i += NTHREADS) {
            int nb = i / 48, k = 2 * (i - 48 * nb);
            const float* fr = sFf + nb * 96;
            float la, lb;
            uint32_t h = pk2(fr[k], fr[k + 1], &la, &lb);
            *(uint32_t*)(sm + A_OFF + nb * 208 + 2 * k) = h;
            *(uint32_t*)(sm + A_OFF + 26624 + nb * 208 + 2 * k) = pk2lo(la, lb);
        }
        __syncthreads();

        // Prefetch seg1 f32 slice (192 floats/node) while seg0 MMA runs
        for (int i = tid; i < R * 48; i += NTHREADS) {
            int nb = i / 48, o = i - 48 * nb;
            cpa16(sF + nb * 768 + 16 * o,
                  x + (size_t)s_node[nb] * IN_SIZE + 96 + 4 * o);
        }
        cpa_commit();

        // ===== seg0: M=128 N=96 K=96 =====
        if (16 * wr < R) {
            float c[6][4];
            #pragma unroll
            for (int j = 0; j < 6; j++)
                #pragma unroll
                for (int q = 0; q < 4; q++) c[j][q] = 0.f;
            const uint32_t ah = sA + (16 * wr + a_row) * 208 + a_k16;
            const uint32_t al = ah + 26624;
            const uint32_t bh = sB + OFF_B0H + (48 * wc + b_row) * 208 + b_k16;
            const uint32_t bl = sB + OFF_B0L + (48 * wc + b_row) * 208 + b_k16;
            #pragma unroll
            for (int kk = 0; kk < 6; kk++) {
                uint32_t A[4], Al[4];
                ldm4(A, ah + 32 * kk);
                ldm4(Al, al + 32 * kk);
                #pragma unroll
                for (int p = 0; p < 3; p++) {
                    uint32_t Bh[4], Bl[4];
                    ldm4(Bh, bh + p * (16 * 208) + 32 * kk);
                    ldm4(Bl, bl + p * (16 * 208) + 32 * kk);
                    mma16816(c[2 * p], A, Bh);
                    mma16816(c[2 * p], Al, Bh);
                    mma16816(c[2 * p], A, Bl);
                    mma16816(c[2 * p + 1], A, Bh + 2);
                    mma16816(c[2 * p + 1], Al, Bh + 2);
                    mma16816(c[2 * p + 1], A, Bl + 2);
                }
            }
            int rA = 16 * wr + (lane >> 2), rB = rA + 8;
            int cb = 48 * wc + 2 * (lane & 3);
            if (rA < R) {
                float* yp = y + (size_t)s_node[rA] * OUT_SIZE;
                #pragma unroll
                for (int j = 0; j < 6; j++)
                    *(float2*)(yp + cb + 8 * j) = make_float2(c[j][0], c[j][1]);
            }
            if (rB < R) {
                float* yp = y + (size_t)s_node[rB] * OUT_SIZE;
                #pragma unroll
                for (int j = 0; j < 6; j++)
                    *(float2*)(yp + cb + 8 * j) = make_float2(c[j][2], c[j][3]);
            }
        }
        cpa_wait();
        __syncthreads();   // seg1 f32 ready; seg0 MMA sA reads done

        // ===== seg1: 3x (M=128 N=64 K=64), A stride 144 =====
        for (int m = 0; m < 3; m++) {
            // convert m: pairs (3k+m, 3(k+1)+m), k even
            for (int i = tid; i < R * 32; i += NTHREADS) {
                int nb = i / 32, k = 2 * (i - 32 * nb);
                const float* fr = sFf + nb * 192;
                float la, lb;
                uint32_t h = pk2(fr[3 * k + m], fr[3 * (k + 1) + m], &la, &lb);
                *(uint32_t*)(sm + A_OFF + nb * 144 + 2 * k) = h;
                *(uint32_t*)(sm + A_OFF + 18432 + nb * 144 + 2 * k) = pk2lo(la, lb);
            }
            __syncthreads();
            if (m == 2) {   // prefetch seg2 f32 (160 floats/node) during last MMA
                for (int i = tid; i < R * 40; i += NTHREADS) {
                    int nb = i / 40, o = i - 40 * nb;
                    cpa16(sF + nb * 640 + 16 * o,
                          x + (size_t)s_node[nb] * IN_SIZE + 288 + 4 * o);
                }
                cpa_commit();
            }
            if (16 * wr < R) {
                float c[4][4];
                #pragma unroll
                for (int j = 0; j < 4; j++)
                    #pragma unroll
                    for (int q = 0; q < 4; q++) c[j][q] = 0.f;
                const uint32_t ah = sA + (16 * wr + a_row) * 144 + a_k16;
                const uint32_t al = ah + 18432;
                const uint32_t bh = sB + OFF_B1H + (32 * wc + b_row) * 144 + b_k16;
                const uint32_t bl = sB + OFF_B1L + (32 * wc + b_row) * 144 + b_k16;
                #pragma unroll
                for (int kk = 0; kk < 4; kk++) {
                    uint32_t A[4], Al[4];
                    ldm4(A, ah + 32 * kk);
                    ldm4(Al, al + 32 * kk);
                    #pragma unroll
                    for (int p = 0; p < 2; p++) {
                        uint32_t Bh[4], Bl[4];
                        ldm4(Bh, bh + p * (16 * 144) + 32 * kk);
                        ldm4(Bl, bl + p * (16 * 144) + 32 * kk);
                        mma16816(c[2 * p], A, Bh);
                        mma16816(c[2 * p], Al, Bh);
                        mma16816(c[2 * p], A, Bl);
                        mma16816(c[2 * p + 1], A, Bh + 2);
                        mma16816(c[2 * p + 1], Al, Bh + 2);
                        mma16816(c[2 * p + 1], A, Bl + 2);
                    }
                }
                int rA = 16 * wr + (lane >> 2), rB = rA + 8;
                int cb = 32 * wc + 2 * (lane & 3);
                if (rA < R) {
                    float* yp = y + (size_t)s_node[rA] * OUT_SIZE + 96 + m;
                    #pragma unroll
                    for (int j = 0; j < 4; j++) {
                        yp[3 * (cb + 8 * j)] = c[j][0];
                        yp[3 * (cb + 8 * j + 1)] = c[j][1];
                    }
                }
                if (rB < R) {
                    float* yp = y + (size_t)s_node[rB] * OUT_SIZE + 96 + m;
                    #pragma unroll
                    for (int j = 0; j < 4; j++) {
                        yp[3 * (cb + 8 * j)] = c[j][2];
                        yp[3 * (cb + 8 * j + 1)] = c[j][3];
                    }
                }
            }
            if (m == 2) cpa_wait();
            __syncthreads();
        }

        // ===== seg2: 5x (M=128 N=32 K=32), A stride 80 =====
        for (int m = 0; m < 5; m++) {
            for (int i = tid; i < R * 16; i += NTHREADS) {
                int nb = i / 16, k = 2 * (i - 16 * nb);
                const float* fr = sFf + nb * 160;
                float la, lb;
                uint32_t h = pk2(fr[5 * k + m], fr[5 * (k + 1) + m], &la, &lb);
                *(uint32_t*)(sm + A_OFF + nb * 80 + 2 * k) = h;
                *(uint32_t*)(sm + A_OFF + 10240 + nb * 80 + 2 * k) = pk2lo(la, lb);
            }
            __syncthreads();
            if (16 * wr < R) {
                float c[2][4];
                #pragma unroll
                for (int j = 0; j < 2; j++)
                    #pragma unroll
                    for (int q = 0; q < 4; q++) c[j][q] = 0.f;
                const uint32_t ah = sA + (16 * wr + a_row) * 80 + a_k16;
                const uint32_t al = ah + 10240;
                const uint32_t bh = sB + OFF_B2H + (16 * wc + b_row) * 80 + b_k16;
                const uint32_t bl = sB + OFF_B2L + (16 * wc + b_row) * 80 + b_k16;
                #pragma unroll
                for (int kk = 0; kk < 2; kk++) {
                    uint32_t A[4], Al[4];
                    ldm4(A, ah + 32 * kk);
                    ldm4(Al, al + 32 * kk);
                    uint32_t Bh[4], Bl[4];
                    ldm4(Bh, bh + 32 * kk);
                    ldm4(Bl, bl + 32 * kk);
                    mma16816(c[0], A, Bh);
                    mma16816(c[0], Al, Bh);
                    mma16816(c[0], A, Bl);
                    mma16816(c[1], A, Bh + 2);
                    mma16816(c[1], Al, Bh + 2);
                    mma16816(c[1], A, Bl + 2);
                }
                int rA = 16 * wr + (lane >> 2), rB = rA + 8;
                int cb = 16 * wc + 2 * (lane & 3);
                if (rA < R) {
                    float* yp = y + (size_t)s_node[rA] * OUT_SIZE + 288 + m;
                    #pragma unroll
                    for (int j = 0; j < 2; j++) {
                        yp[5 * (cb + 8 * j)] = c[j][0];
                        yp[5 * (cb + 8 * j + 1)] = c[j][1];
                    }
                }
                if (rB < R) {
                    float* yp = y + (size_t)s_node[rB] * OUT_SIZE + 288 + m;
                    #pragma unroll
                    for (int j = 0; j < 2; j++) {
                        yp[5 * (cb + 8 * j)] = c[j][2];
                        yp[5 * (cb + 8 * j + 1)] = c[j][3];
                    }
                }
            }
            __syncthreads();
        }
    }
}

// ---------------------------------------------------------------------------
// Launch
// ---------------------------------------------------------------------------
extern "C" void kernel_launch(void* const* d_in, const int* in_sizes, int n_in,
                              void* d_out, int out_size)
{
    const float* W  = (const float*)d_in[0];   // [64, 14336]
    const float* x  = (const float*)d_in[1];   // [16384, 448]
    const void*  ix = d_in[2];                 // [16384] int32 or int64
    float* y = (float*)d_out;                  // [16384, 448]

    cudaFuncSetAttribute(compute_kernel,
                         cudaFuncAttributeMaxDynamicSharedMemorySize, SMEM_BYTES);

    wconv_kernel<<<NE, PTHREADS>>>(W);
    hist_kernel<<<NHB, PTHREADS>>>(ix);
    finish_kernel<<<NHB, PTHREADS>>>(ix);
    compute_kernel<<<GRID_COMPUTE, NTHREADS, SMEM_BYTES>>>(x, y);
}